// round 1
// baseline (speedup 1.0000x reference)
#include <cuda_runtime.h>

#define FULLMASK 0xffffffffu

// Shared-memory layout (floats), dynamic smem:
//   W2s : 64 rows x 260 stride (only [0,256) of each row used)
//   W1s : 16 x 64
//   b1s : 64
//   b2s : 256
//   Ash : 8 warps x (16 rows x 20 stride)
#define W2_STRIDE 260
#define ASH_STRIDE 20
#define W2S_OFF 0
#define W1S_OFF (64 * W2_STRIDE)            // 16640
#define B1S_OFF (W1S_OFF + 16 * 64)         // 17664
#define B2S_OFF (B1S_OFF + 64)              // 17728
#define ASH_OFF (B2S_OFF + 256)             // 17984
#define ASH_PER_WARP (16 * ASH_STRIDE)      // 320
#define SMEM_FLOATS (ASH_OFF + 8 * ASH_PER_WARP)   // 20544
#define SMEM_BYTES (SMEM_FLOATS * 4)               // 82176

// One ODE RHS evaluation for one point (one warp).
// zs: this lane's element of the 32-dim state [x(16), v(16)].
// Returns this lane's element of f(z) = [v, dv].
__device__ __noinline__ float geo_f(float zs, int lane, int warp)
{
    extern __shared__ float smem[];
    const float* W2s = smem + W2S_OFF;
    const float* W1s = smem + W1S_OFF;
    const float* b1s = smem + B1S_OFF;
    const float* b2s = smem + B2S_OFF;
    float* Ash = smem + ASH_OFF + warp * ASH_PER_WARP;

    const int i16 = lane & 15;

    // ---- materialize x, v replicated in registers ----
    float x[16], v[16];
#pragma unroll
    for (int a = 0; a < 16; a++) {
        x[a] = __shfl_sync(FULLMASK, zs, a);
        v[a] = __shfl_sync(FULLMASK, zs, 16 + a);
    }

    // ---- hidden layer: this lane owns channels c0=lane, c1=lane+32 ----
    float pre0 = b1s[lane], pre1 = b1s[lane + 32];
#pragma unroll
    for (int a = 0; a < 16; a++) {
        pre0 = fmaf(x[a], W1s[a * 64 + lane], pre0);
        pre1 = fmaf(x[a], W1s[a * 64 + lane + 32], pre1);
    }
    const float h0 = tanhf(pre0);
    const float h1 = tanhf(pre1);
    const float th0 = fmaf(-h0, h0, 1.0f);   // 1 - h^2
    const float th1 = fmaf(-h1, h1, 1.0f);

    // ---- A = h @ W2 + b2 (flat 256), lane owns pq in [4l,4l+4) and [128+4l,128+4l+4) ----
    float4 acc0 = *(const float4*)(b2s + 4 * lane);
    float4 acc1 = *(const float4*)(b2s + 128 + 4 * lane);
#pragma unroll 8
    for (int c = 0; c < 32; c++) {
        const float hc = __shfl_sync(FULLMASK, h0, c);
        const float4 w0 = *(const float4*)(W2s + c * W2_STRIDE + 4 * lane);
        const float4 w1 = *(const float4*)(W2s + c * W2_STRIDE + 128 + 4 * lane);
        acc0.x = fmaf(hc, w0.x, acc0.x); acc0.y = fmaf(hc, w0.y, acc0.y);
        acc0.z = fmaf(hc, w0.z, acc0.z); acc0.w = fmaf(hc, w0.w, acc0.w);
        acc1.x = fmaf(hc, w1.x, acc1.x); acc1.y = fmaf(hc, w1.y, acc1.y);
        acc1.z = fmaf(hc, w1.z, acc1.z); acc1.w = fmaf(hc, w1.w, acc1.w);
    }
#pragma unroll 8
    for (int c = 0; c < 32; c++) {
        const float hc = __shfl_sync(FULLMASK, h1, c);
        const float4 w0 = *(const float4*)(W2s + (c + 32) * W2_STRIDE + 4 * lane);
        const float4 w1 = *(const float4*)(W2s + (c + 32) * W2_STRIDE + 128 + 4 * lane);
        acc0.x = fmaf(hc, w0.x, acc0.x); acc0.y = fmaf(hc, w0.y, acc0.y);
        acc0.z = fmaf(hc, w0.z, acc0.z); acc0.w = fmaf(hc, w0.w, acc0.w);
        acc1.x = fmaf(hc, w1.x, acc1.x); acc1.y = fmaf(hc, w1.y, acc1.y);
        acc1.z = fmaf(hc, w1.z, acc1.z); acc1.w = fmaf(hc, w1.w, acc1.w);
    }

    // ---- store A to per-warp shared tile Ash[p][q], row stride 20 ----
    __syncwarp();  // previous eval's Ash readers must be done
    {
        const int prow = lane >> 2;
        const int qcol = (lane & 3) * 4;
        *(float4*)(Ash + prow * ASH_STRIDE + qcol) = acc0;           // pq = 4*lane     -> p = lane>>2
        *(float4*)(Ash + (8 + prow) * ASH_STRIDE + qcol) = acc1;     // pq = 128+4*lane -> p = 8+(lane>>2)
    }
    __syncwarp();

    // ---- s = A^T v  (lane computes s[q=i16], duplicated across halves) ----
    float sq = 0.0f;
#pragma unroll
    for (int p = 0; p < 16; p++)
        sq = fmaf(Ash[p * ASH_STRIDE + i16], v[p], sq);
    float sv[16];
#pragma unroll
    for (int q = 0; q < 16; q++)
        sv[q] = __shfl_sync(FULLMASK, sq, q);

    // ---- m_c = v^T B_c s for this lane's channels c0=lane, c1=lane+32 ----
    float m0 = 0.0f, m1 = 0.0f;
#pragma unroll
    for (int p = 0; p < 16; p++) {
        const float4* r0 = (const float4*)(W2s + lane * W2_STRIDE + 16 * p);
        const float4* r1 = (const float4*)(W2s + (lane + 32) * W2_STRIDE + 16 * p);
        float d0 = 0.0f, d1 = 0.0f;
#pragma unroll
        for (int tq = 0; tq < 4; tq++) {
            const float4 w0 = r0[tq];
            const float4 w1 = r1[tq];
            d0 = fmaf(w0.x, sv[4 * tq + 0], d0);
            d0 = fmaf(w0.y, sv[4 * tq + 1], d0);
            d0 = fmaf(w0.z, sv[4 * tq + 2], d0);
            d0 = fmaf(w0.w, sv[4 * tq + 3], d0);
            d1 = fmaf(w1.x, sv[4 * tq + 0], d1);
            d1 = fmaf(w1.y, sv[4 * tq + 1], d1);
            d1 = fmaf(w1.z, sv[4 * tq + 2], d1);
            d1 = fmaf(w1.w, sv[4 * tq + 3], d1);
        }
        m0 = fmaf(v[p], d0, m0);
        m1 = fmaf(v[p], d1, m1);
    }

    // ---- u_i = 2 * sum_c W1[i][c] * th_c * m_c : per-lane partial then warp reduce ----
    const float cm0 = 2.0f * th0 * m0;
    const float cm1 = 2.0f * th1 * m1;
    float up[16];
#pragma unroll
    for (int i = 0; i < 16; i++)
        up[i] = fmaf(W1s[i * 64 + lane], cm0, W1s[i * 64 + lane + 32] * cm1);
#pragma unroll
    for (int off = 16; off >= 1; off >>= 1) {
#pragma unroll
        for (int i = 0; i < 16; i++)
            up[i] += __shfl_xor_sync(FULLMASK, up[i], off);
    }
    // rhs for this lane's row: rhs = u[i16]  (static select chain)
    float rhs = up[0];
#pragma unroll
    for (int i = 1; i < 16; i++)
        rhs = (i16 == i) ? up[i] : rhs;

    // ---- g row i16 : g[i][j] = sum_q A[i][q]*A[j][q] + (i==j) ----
    float ar[16];
#pragma unroll
    for (int tq = 0; tq < 4; tq++) {
        const float4 w = *(const float4*)(Ash + i16 * ASH_STRIDE + 4 * tq);
        ar[4 * tq + 0] = w.x; ar[4 * tq + 1] = w.y;
        ar[4 * tq + 2] = w.z; ar[4 * tq + 3] = w.w;
    }
    float grow[16];
#pragma unroll
    for (int j = 0; j < 16; j++) {
        float gj = (j == i16) ? 1.0f : 0.0f;
#pragma unroll
        for (int tq = 0; tq < 4; tq++) {
            const float4 w = *(const float4*)(Ash + j * ASH_STRIDE + 4 * tq);  // broadcast
            gj = fmaf(ar[4 * tq + 0], w.x, gj);
            gj = fmaf(ar[4 * tq + 1], w.y, gj);
            gj = fmaf(ar[4 * tq + 2], w.z, gj);
            gj = fmaf(ar[4 * tq + 3], w.w, gj);
        }
        grow[j] = gj;
    }

    // ---- solve g y = u (SPD, no pivoting). Lane l holds row i16 of [g | rhs]. ----
#pragma unroll
    for (int k = 0; k < 15; k++) {
        const float piv = __shfl_sync(FULLMASK, grow[k], k);
        const float prhs = __shfl_sync(FULLMASK, rhs, k);
        const float ipiv = 1.0f / piv;
        const float fac = grow[k] * ipiv;
        const bool act = (i16 > k);
#pragma unroll
        for (int q = k + 1; q < 16; q++) {
            const float pq = __shfl_sync(FULLMASK, grow[q], k);
            if (act) grow[q] = fmaf(-fac, pq, grow[q]);
        }
        if (act) rhs = fmaf(-fac, prhs, rhs);
    }
    // back substitution; dv = -0.5 * y, collected distributed on lanes 16..31
    float dvl = 0.0f;
#pragma unroll
    for (int k = 15; k >= 0; k--) {
        const float num = __shfl_sync(FULLMASK, rhs, k);
        const float den = __shfl_sync(FULLMASK, grow[k], k);
        const float yk = num / den;
        if (i16 < k) rhs = fmaf(-grow[k], yk, rhs);
        if (lane == k + 16) dvl = -0.5f * yk;
    }

    // f(z) = [v, dv]: lanes 0..15 output v (= zs of lane+16), lanes 16..31 output dv
    const float vpart = __shfl_sync(FULLMASK, zs, (lane + 16) & 31);
    return (lane < 16) ? vpart : dvl;
}

__global__ __launch_bounds__(256, 2)
void NeuralGeodesicFlows_45784351375900_kernel(
    const float* __restrict__ z_in,
    const float* __restrict__ t_ptr,
    const float* __restrict__ W1,
    const float* __restrict__ b1,
    const float* __restrict__ W2,
    const float* __restrict__ b2,
    const int* __restrict__ ns_ptr,
    float* __restrict__ z_out,
    int B)
{
    extern __shared__ float smem[];
    float* W2s = smem + W2S_OFF;
    float* W1s = smem + W1S_OFF;
    float* b1s = smem + B1S_OFF;
    float* b2s = smem + B2S_OFF;

    const int tid = threadIdx.x;

    // cooperative weight load (padded W2 rows)
    for (int idx = tid; idx < 64 * 256; idx += 256) {
        const int c = idx >> 8;
        const int pq = idx & 255;
        W2s[c * W2_STRIDE + pq] = W2[idx];
    }
    for (int idx = tid; idx < 16 * 64; idx += 256)
        W1s[idx] = W1[idx];
    if (tid < 64) b1s[tid] = b1[tid];
    b2s[tid] = b2[tid];
    __syncthreads();

    const int warp = tid >> 5;
    const int lane = tid & 31;
    const int point = blockIdx.x * 8 + warp;
    if (point >= B) return;

    float zl = z_in[point * 32 + lane];
    const float t = *t_ptr;
    const int ns = *ns_ptr;
    const float dt = t / (float)ns;

    for (int s = 0; s < ns; s++) {
        const float k1 = geo_f(zl, lane, warp);
        const float k2 = geo_f(fmaf(0.5f * dt, k1, zl), lane, warp);
        const float k3 = geo_f(fmaf(0.5f * dt, k2, zl), lane, warp);
        const float k4 = geo_f(fmaf(dt, k3, zl), lane, warp);
        zl = fmaf(dt * (1.0f / 6.0f),
                  k1 + 2.0f * k2 + 2.0f * k3 + k4, zl);
    }
    z_out[point * 32 + lane] = zl;
}

extern "C" void kernel_launch(void* const* d_in, const int* in_sizes, int n_in,
                              void* d_out, int out_size)
{
    const float* z  = (const float*)d_in[0];
    const float* t  = (const float*)d_in[1];
    const float* W1 = (const float*)d_in[2];
    const float* b1 = (const float*)d_in[3];
    const float* W2 = (const float*)d_in[4];
    const float* b2 = (const float*)d_in[5];
    const int*   ns = (const int*)d_in[6];
    float* out = (float*)d_out;

    const int B = in_sizes[0] / 32;
    const int grid = (B + 7) / 8;

    cudaFuncSetAttribute(NeuralGeodesicFlows_45784351375900_kernel,
                         cudaFuncAttributeMaxDynamicSharedMemorySize, SMEM_BYTES);
    NeuralGeodesicFlows_45784351375900_kernel<<<grid, 256, SMEM_BYTES>>>(
        z, t, W1, b1, W2, b2, ns, out, B);
}

// round 2
// speedup vs baseline: 1.4830x; 1.4830x over previous
#include <cuda_runtime.h>

#define FULLMASK 0xffffffffu

// ---- shared layout (float offsets) ----
#define W2_STRIDE 260                  // 64 rows x 260 (256 used)
#define TS 20                          // A-tile row stride
#define TILE 336                       // per-point A-tile stride (16*20=320 used; 336%32=16 for bank shift)
#define W1R_STRIDE 68                  // W1 row-major padded: 16 x 68
#define W1T_STRIDE 20                  // W1 transposed:       64 x 20
#define WSC_STRIDE 80                  // per-point w-scratch stride (80%32=16)

#define W2S_OFF 0
#define W1R_OFF (64 * W2_STRIDE)                  // 16640
#define W1T_OFF (W1R_OFF + 16 * W1R_STRIDE)       // 17728
#define B1S_OFF (W1T_OFF + 64 * W1T_STRIDE)       // 19008
#define B2S_OFF (B1S_OFF + 64)                    // 19072
#define ASH_OFF (B2S_OFF + 256)                   // 19328
#define WSC_OFF (ASH_OFF + 16 * TILE)             // 24704
#define SMEM_FLOATS (WSC_OFF + 16 * WSC_STRIDE)   // 25984
#define SMEM_BYTES (SMEM_FLOATS * 4)              // 103936

// One acceleration evaluation: returns dv_{i16} for this lane's half-point.
// xl, vl: this lane's x_{i16}, v_{i16} of its half's point.
__device__ __noinline__ float geo_dv(float xl, float vl, int lane, int i16, int warp)
{
    extern __shared__ float smem[];
    const float* W2s = smem + W2S_OFF;
    const float* W1r = smem + W1R_OFF;
    const float* W1t = smem + W1T_OFF;
    const float* b1s = smem + B1S_OFF;
    const float* b2s = smem + B2S_OFF;
    float* tile0 = smem + ASH_OFF + (warp * 2) * TILE;
    float* tile1 = tile0 + TILE;
    const int half = lane >> 4;
    float* tileown = tile0 + half * TILE;
    float* wscown = smem + WSC_OFF + (warp * 2 + half) * WSC_STRIDE;

    // ---- replicate x, v within own half ----
    float x[16], v[16];
#pragma unroll
    for (int a = 0; a < 16; a++) {
        x[a] = __shfl_sync(FULLMASK, xl, a, 16);
        v[a] = __shfl_sync(FULLMASK, vl, a, 16);
    }

    // ---- hidden layer: lane owns channels c = i16 + 16j of its own point ----
    float h[4], th[4];
#pragma unroll
    for (int j = 0; j < 4; j++) {
        const int c = i16 + 16 * j;
        float pre = b1s[c];
        const float4* wr = (const float4*)(W1t + c * W1T_STRIDE);
#pragma unroll
        for (int t = 0; t < 4; t++) {
            const float4 w = wr[t];
            pre = fmaf(w.x, x[4 * t + 0], pre);
            pre = fmaf(w.y, x[4 * t + 1], pre);
            pre = fmaf(w.z, x[4 * t + 2], pre);
            pre = fmaf(w.w, x[4 * t + 3], pre);
        }
        h[j] = tanhf(pre);
        th[j] = fmaf(-h[j], h[j], 1.0f);
    }

    // ---- A pass (warp-wide, both points share every W2 load) ----
    float4 A0a = ((const float4*)b2s)[lane];
    float4 A0b = ((const float4*)b2s)[32 + lane];
    float4 A1a = A0a;
    float4 A1b = A0b;
#pragma unroll
    for (int j = 0; j < 4; j++) {
#pragma unroll 4
        for (int r16 = 0; r16 < 16; r16++) {
            const int r = 16 * j + r16;
            const float h0 = __shfl_sync(FULLMASK, h[j], r16);
            const float h1 = __shfl_sync(FULLMASK, h[j], 16 + r16);
            const float4 wa = *(const float4*)(W2s + r * W2_STRIDE + 4 * lane);
            const float4 wb = *(const float4*)(W2s + r * W2_STRIDE + 128 + 4 * lane);
            A0a.x = fmaf(h0, wa.x, A0a.x); A0a.y = fmaf(h0, wa.y, A0a.y);
            A0a.z = fmaf(h0, wa.z, A0a.z); A0a.w = fmaf(h0, wa.w, A0a.w);
            A0b.x = fmaf(h0, wb.x, A0b.x); A0b.y = fmaf(h0, wb.y, A0b.y);
            A0b.z = fmaf(h0, wb.z, A0b.z); A0b.w = fmaf(h0, wb.w, A0b.w);
            A1a.x = fmaf(h1, wa.x, A1a.x); A1a.y = fmaf(h1, wa.y, A1a.y);
            A1a.z = fmaf(h1, wa.z, A1a.z); A1a.w = fmaf(h1, wa.w, A1a.w);
            A1b.x = fmaf(h1, wb.x, A1b.x); A1b.y = fmaf(h1, wb.y, A1b.y);
            A1b.z = fmaf(h1, wb.z, A1b.z); A1b.w = fmaf(h1, wb.w, A1b.w);
        }
    }

    // ---- stage A tiles (both points) ----
    __syncwarp();
    {
        const int p = lane >> 2;
        const int q4 = (lane & 3) * 4;
        *(float4*)(tile0 + p * TS + q4) = A0a;
        *(float4*)(tile0 + (8 + p) * TS + q4) = A0b;
        *(float4*)(tile1 + p * TS + q4) = A1a;
        *(float4*)(tile1 + (8 + p) * TS + q4) = A1b;
    }
    __syncwarp();

    // ---- s = A^T v (per half): lane computes s_{i16} ----
    float sq = 0.0f;
#pragma unroll
    for (int p = 0; p < 16; p++)
        sq = fmaf(tileown[p * TS + i16], v[p], sq);
    float sv[16];
#pragma unroll
    for (int q = 0; q < 16; q++)
        sv[q] = __shfl_sync(FULLMASK, sq, q, 16);

    // ---- m_c = v^T B_c s ; lane owns rows c = i16 + 16j of its own point ----
    // corresponding lanes of the two halves read identical W2 addresses (broadcast)
    float wv[4];
#pragma unroll
    for (int j = 0; j < 4; j++) {
        const float* R = W2s + (i16 + 16 * j) * W2_STRIDE;
        float m = 0.0f;
#pragma unroll
        for (int p = 0; p < 16; p++) {
            const float4* ch = (const float4*)(R + 16 * p);
            float d = 0.0f;
#pragma unroll
            for (int t = 0; t < 4; t++) {
                const float4 w = ch[t];
                d = fmaf(w.x, sv[4 * t + 0], d);
                d = fmaf(w.y, sv[4 * t + 1], d);
                d = fmaf(w.z, sv[4 * t + 2], d);
                d = fmaf(w.w, sv[4 * t + 3], d);
            }
            m = fmaf(v[p], d, m);
        }
        wv[j] = 2.0f * th[j] * m;
    }

    // ---- stage w_c, then u_{i16} = W1 row i16 . w  (no shuffles needed) ----
    __syncwarp();
#pragma unroll
    for (int j = 0; j < 4; j++)
        wscown[i16 + 16 * j] = wv[j];
    __syncwarp();

    float rhs = 0.0f;
    {
        const float4* wr = (const float4*)(W1r + i16 * W1R_STRIDE);
        const float4* wc = (const float4*)wscown;
#pragma unroll
        for (int t = 0; t < 16; t++) {
            const float4 a = wr[t];
            const float4 b = wc[t];
            rhs = fmaf(a.x, b.x, rhs);
            rhs = fmaf(a.y, b.y, rhs);
            rhs = fmaf(a.z, b.z, rhs);
            rhs = fmaf(a.w, b.w, rhs);
        }
    }

    // ---- g row i16 of own point: g[i][j] = A[i].A[j] + (i==j) ----
    float ar[16];
#pragma unroll
    for (int t = 0; t < 4; t++) {
        const float4 w = *(const float4*)(tileown + i16 * TS + 4 * t);
        ar[4 * t + 0] = w.x; ar[4 * t + 1] = w.y;
        ar[4 * t + 2] = w.z; ar[4 * t + 3] = w.w;
    }
    float grow[16];
#pragma unroll
    for (int jr = 0; jr < 16; jr++) {
        float gj = (jr == i16) ? 1.0f : 0.0f;
#pragma unroll
        for (int t = 0; t < 4; t++) {
            const float4 w = *(const float4*)(tileown + jr * TS + 4 * t);  // half-broadcast
            gj = fmaf(ar[4 * t + 0], w.x, gj);
            gj = fmaf(ar[4 * t + 1], w.y, gj);
            gj = fmaf(ar[4 * t + 2], w.z, gj);
            gj = fmaf(ar[4 * t + 3], w.w, gj);
        }
        grow[jr] = gj;
    }

    // ---- solve g y = u per half (SPD, no pivoting), width-16 shuffles ----
#pragma unroll
    for (int k = 0; k < 15; k++) {
        const float piv = __shfl_sync(FULLMASK, grow[k], k, 16);
        const float prhs = __shfl_sync(FULLMASK, rhs, k, 16);
        const float ipiv = __fdividef(1.0f, piv);
        const float fac = grow[k] * ipiv;
        const bool act = (i16 > k);
#pragma unroll
        for (int q = k + 1; q < 16; q++) {
            const float pq = __shfl_sync(FULLMASK, grow[q], k, 16);
            if (act) grow[q] = fmaf(-fac, pq, grow[q]);
        }
        if (act) rhs = fmaf(-fac, prhs, rhs);
    }
    float dvl = 0.0f;
#pragma unroll
    for (int k = 15; k >= 0; k--) {
        const float num = __shfl_sync(FULLMASK, rhs, k, 16);
        const float den = __shfl_sync(FULLMASK, grow[k], k, 16);
        const float yk = __fdividef(num, den);
        if (i16 < k) rhs = fmaf(-grow[k], yk, rhs);
        if (i16 == k) dvl = -0.5f * yk;
    }
    return dvl;
}

__global__ __launch_bounds__(256, 2)
void NeuralGeodesicFlows_45784351375900_kernel(
    const float* __restrict__ z_in,
    const float* __restrict__ t_ptr,
    const float* __restrict__ W1,
    const float* __restrict__ b1,
    const float* __restrict__ W2,
    const float* __restrict__ b2,
    const int* __restrict__ ns_ptr,
    float* __restrict__ z_out,
    int B)
{
    extern __shared__ float smem[];
    const int tid = threadIdx.x;

    // cooperative weight staging
    for (int idx = tid; idx < 64 * 256; idx += 256)
        smem[W2S_OFF + (idx >> 8) * W2_STRIDE + (idx & 255)] = W2[idx];
    for (int idx = tid; idx < 16 * 64; idx += 256) {
        const int a = idx >> 6, c = idx & 63;
        const float w = W1[idx];
        smem[W1R_OFF + a * W1R_STRIDE + c] = w;
        smem[W1T_OFF + c * W1T_STRIDE + a] = w;
    }
    if (tid < 64) smem[B1S_OFF + tid] = b1[tid];
    smem[B2S_OFF + tid] = b2[tid];
    __syncthreads();

    const int warp = tid >> 5;
    const int lane = tid & 31;
    const int i16 = lane & 15;
    const int half = lane >> 4;
    const int point = blockIdx.x * 16 + warp * 2 + half;
    if (point >= B) return;

    float zx = z_in[point * 32 + i16];
    float zv = z_in[point * 32 + 16 + i16];
    const float t = *t_ptr;
    const int ns = *ns_ptr;
    const float dt = t / (float)ns;
    const float hdt = 0.5f * dt;
    const float dt6 = dt * (1.0f / 6.0f);

    for (int s = 0; s < ns; s++) {
        const float a1 = geo_dv(zx, zv, lane, i16, warp);
        const float v2 = fmaf(hdt, a1, zv);
        const float a2 = geo_dv(fmaf(hdt, zv, zx), v2, lane, i16, warp);
        const float v3 = fmaf(hdt, a2, zv);
        const float a3 = geo_dv(fmaf(hdt, v2, zx), v3, lane, i16, warp);
        const float v4 = fmaf(dt, a3, zv);
        const float a4 = geo_dv(fmaf(dt, v3, zx), v4, lane, i16, warp);
        zx = fmaf(dt6, zv + 2.0f * v2 + 2.0f * v3 + v4, zx);
        zv = fmaf(dt6, a1 + 2.0f * a2 + 2.0f * a3 + a4, zv);
    }
    z_out[point * 32 + i16] = zx;
    z_out[point * 32 + 16 + i16] = zv;
}

extern "C" void kernel_launch(void* const* d_in, const int* in_sizes, int n_in,
                              void* d_out, int out_size)
{
    const float* z  = (const float*)d_in[0];
    const float* t  = (const float*)d_in[1];
    const float* W1 = (const float*)d_in[2];
    const float* b1 = (const float*)d_in[3];
    const float* W2 = (const float*)d_in[4];
    const float* b2 = (const float*)d_in[5];
    const int*   ns = (const int*)d_in[6];
    float* out = (float*)d_out;

    const int B = in_sizes[0] / 32;
    const int grid = (B + 15) / 16;

    cudaFuncSetAttribute(NeuralGeodesicFlows_45784351375900_kernel,
                         cudaFuncAttributeMaxDynamicSharedMemorySize, SMEM_BYTES);
    NeuralGeodesicFlows_45784351375900_kernel<<<grid, 256, SMEM_BYTES>>>(
        z, t, W1, b1, W2, b2, ns, out, B);
}